// round 11
// baseline (speedup 1.0000x reference)
#include <cuda_runtime.h>

// EpochedFutureFill == causal FIR conv, B=256, T=L=65536, via FFT of N=131072.
// Four-step decomposition: N = 256 (n1, stride 512) x 512 (n2, contiguous).
//   K0 : build twiddle tables (K1/K4 only)
//   K1 : pack + FFT256 over n1 (strided) + w_N^{-n2 k1}  -> U[k1][n2]
//   K2f: filter row: warp-FFT512 -> F (slot layout, scaled 1/N)
//   K23: warp-autonomous FFT512 fwd + multiply + IFFT512 + w_N^{+n2 k1} (in place)
//   K4 : IFFT256 over k1 (strided) + causal unpack to y
// R11: complex add/sub as packed f32x2 PTX (sm_100+ only; ptxas never emits it
// from C++). dft4 restructured so the +-i rotation is 4 scalar FADDs.

namespace {
constexpr int N_FFT = 131072;
constexpr int T_LEN = 65536;
constexpr int PAIRS = 128;
constexpr int ROWS_F = 129;
constexpr float TWO_PI = 6.28318530717958647692f;
constexpr float INV_N = 1.0f / (float)N_FFT;
}

// digit-reverse for radix-4^2 of 16: slot(p) = ((p&3)<<2)|(p>>2)  (involution)
#define DR16(p) ((((p) & 3) << 2) | ((p) >> 2))

// Scratch (no cudaMalloc allowed).
__device__ float2 g_buf[(size_t)ROWS_F * N_FFT];
__device__ float4 g_fspec4[N_FFT / 2];  // F in per-lane-contiguous slot layout
__device__ float2 g_t64[8 * 8];
__device__ float2 g_t256[4 * 64];

// ---- packed f32x2 complex add/sub (pack/unpack movs fold into reg pairs) ----
__device__ __forceinline__ float2 cadd(float2 a, float2 b) {
    unsigned long long ua, ub, uc;
    asm("mov.b64 %0, {%1, %2};" : "=l"(ua) : "f"(a.x), "f"(a.y));
    asm("mov.b64 %0, {%1, %2};" : "=l"(ub) : "f"(b.x), "f"(b.y));
    asm("add.rn.f32x2 %0, %1, %2;" : "=l"(uc) : "l"(ua), "l"(ub));
    float2 r;
    asm("mov.b64 {%0, %1}, %2;" : "=f"(r.x), "=f"(r.y) : "l"(uc));
    return r;
}
__device__ __forceinline__ float2 csub(float2 a, float2 b) {
    unsigned long long ua, ub, uc;
    asm("mov.b64 %0, {%1, %2};" : "=l"(ua) : "f"(a.x), "f"(a.y));
    asm("mov.b64 %0, {%1, %2};" : "=l"(ub) : "f"(b.x), "f"(b.y));
    asm("sub.rn.f32x2 %0, %1, %2;" : "=l"(uc) : "l"(ua), "l"(ub));
    float2 r;
    asm("mov.b64 {%0, %1}, %2;" : "=f"(r.x), "=f"(r.y) : "l"(uc));
    return r;
}
__device__ __forceinline__ float2 cmul(float2 a, float2 b) {
    return make_float2(fmaf(a.x, b.x, -a.y * b.y), fmaf(a.x, b.y, a.y * b.x));
}
__device__ __forceinline__ float2 cmulc(float2 a, float2 b) {  // a * conj(b)
    return make_float2(fmaf(a.x, b.x, a.y * b.y), fmaf(a.y, b.x, -a.x * b.y));
}
template <int DIR>
__device__ __forceinline__ float2 cmuli(float2 a) {  // * (i*DIR)
    return (DIR < 0) ? make_float2(a.y, -a.x) : make_float2(-a.y, a.x);
}

// exp(-2*pi*i*j/32), compile-time after unrolling -> FFMA-imm operands.
__device__ __forceinline__ float2 w32f(int j) {
    switch (j & 15) {
        case 0:  return make_float2(1.0f, 0.0f);
        case 1:  return make_float2(0.9807852804032304f, -0.19509032201612827f);
        case 2:  return make_float2(0.9238795325112868f, -0.3826834323650898f);
        case 3:  return make_float2(0.8314696123025452f, -0.5555702330196022f);
        case 4:  return make_float2(0.7071067811865476f, -0.7071067811865476f);
        case 5:  return make_float2(0.5555702330196022f, -0.8314696123025452f);
        case 6:  return make_float2(0.3826834323650898f, -0.9238795325112868f);
        case 7:  return make_float2(0.19509032201612827f, -0.9807852804032304f);
        case 8:  return make_float2(0.0f, -1.0f);
        case 9:  return make_float2(-0.19509032201612827f, -0.9807852804032304f);
        case 10: return make_float2(-0.3826834323650898f, -0.9238795325112868f);
        case 11: return make_float2(-0.5555702330196022f, -0.8314696123025452f);
        case 12: return make_float2(-0.7071067811865476f, -0.7071067811865476f);
        case 13: return make_float2(-0.8314696123025452f, -0.5555702330196022f);
        case 14: return make_float2(-0.9238795325112868f, -0.3826834323650898f);
        default: return make_float2(-0.9807852804032304f, -0.19509032201612827f);
    }
}

// dft4: packed adds for the real/real paths, scalar FADDs for the +-i rotation.
template <int DIR>
__device__ __forceinline__ void dft4(float2 v[4]) {
    float2 t0 = cadd(v[0], v[2]);
    float2 t1 = cadd(v[1], v[3]);
    float2 t2 = csub(v[0], v[2]);
    float2 d  = csub(v[1], v[3]);
    v[0] = cadd(t0, t1);
    v[2] = csub(t0, t1);
    if (DIR < 0) {
        v[1] = make_float2(t2.x + d.y, t2.y - d.x);
        v[3] = make_float2(t2.x - d.y, t2.y + d.x);
    } else {
        v[1] = make_float2(t2.x - d.y, t2.y + d.x);
        v[3] = make_float2(t2.x + d.y, t2.y - d.x);
    }
}

template <int DIR>
__device__ __forceinline__ void dft8(float2 v[8]) {
    const float C = 0.70710678118654752440f;
    float2 b[4], d[4];
#pragma unroll
    for (int i = 0; i < 4; i++) {
        b[i] = cadd(v[i], v[i + 4]);
        d[i] = csub(v[i], v[i + 4]);
    }
    d[1] = cmul(d[1], make_float2(C, (float)DIR * C));
    d[2] = cmuli<DIR>(d[2]);
    d[3] = cmul(d[3], make_float2(-C, (float)DIR * C));
    dft4<DIR>(b);
    dft4<DIR>(d);
    v[0] = b[0]; v[2] = b[1]; v[4] = b[2]; v[6] = b[3];
    v[1] = d[0]; v[3] = d[1]; v[5] = d[2]; v[7] = d[3];
}

// In-place DIF radix-4^2 16-pt DFT. Input natural; output: slot m holds X[DR16(m)].
template <int DIR>
__device__ __forceinline__ void dft16_dif(float2 v[16]) {
    const float C1 = 0.92387953251128674f, S1 = 0.38268343236508978f;
    const float C2 = 0.70710678118654752f;
    const float D = (float)DIR;
    const float2 w1 = make_float2(C1, D * S1), w2 = make_float2(C2, D * C2);
    const float2 w3 = make_float2(S1, D * C1), w6 = make_float2(-C2, D * C2);
    const float2 w9 = make_float2(-C1, -D * S1);
#pragma unroll
    for (int j = 0; j < 4; j++) {
        float2 a[4] = {v[j], v[j + 4], v[j + 8], v[j + 12]};
        dft4<DIR>(a);
        if (j == 1) { a[1] = cmul(a[1], w1); a[2] = cmul(a[2], w2); a[3] = cmul(a[3], w3); }
        else if (j == 2) { a[1] = cmul(a[1], w2); a[2] = cmuli<DIR>(a[2]); a[3] = cmul(a[3], w6); }
        else if (j == 3) { a[1] = cmul(a[1], w3); a[2] = cmul(a[2], w6); a[3] = cmul(a[3], w9); }
        v[j] = a[0]; v[j + 4] = a[1]; v[j + 8] = a[2]; v[j + 12] = a[3];
    }
#pragma unroll
    for (int q = 0; q < 4; q++) {
        float2 a[4] = {v[4 * q], v[4 * q + 1], v[4 * q + 2], v[4 * q + 3]};
        dft4<DIR>(a);
        v[4 * q] = a[0]; v[4 * q + 1] = a[1]; v[4 * q + 2] = a[2]; v[4 * q + 3] = a[3];
    }
}

// In-place DIT radix-4^2 16-pt DFT. Input: slot m holds in[DR16(m)]. Output NATURAL.
template <int DIR>
__device__ __forceinline__ void dft16_dit(float2 v[16]) {
    const float C1 = 0.92387953251128674f, S1 = 0.38268343236508978f;
    const float C2 = 0.70710678118654752f;
    const float D = (float)DIR;
    const float2 w1 = make_float2(C1, D * S1), w2 = make_float2(C2, D * C2);
    const float2 w3 = make_float2(S1, D * C1), w6 = make_float2(-C2, D * C2);
    const float2 w9 = make_float2(-C1, -D * S1);
#pragma unroll
    for (int q = 0; q < 4; q++) {
        float2 a[4] = {v[4 * q], v[4 * q + 1], v[4 * q + 2], v[4 * q + 3]};
        dft4<DIR>(a);
        if (q == 1) { a[1] = cmul(a[1], w1); a[2] = cmul(a[2], w2); a[3] = cmul(a[3], w3); }
        else if (q == 2) { a[1] = cmul(a[1], w2); a[2] = cmuli<DIR>(a[2]); a[3] = cmul(a[3], w6); }
        else if (q == 3) { a[1] = cmul(a[1], w3); a[2] = cmul(a[2], w6); a[3] = cmul(a[3], w9); }
        v[4 * q] = a[0]; v[4 * q + 1] = a[1]; v[4 * q + 2] = a[2]; v[4 * q + 3] = a[3];
    }
#pragma unroll
    for (int u = 0; u < 4; u++) {
        float2 a[4] = {v[u], v[u + 4], v[u + 8], v[u + 12]};
        dft4<DIR>(a);
        v[u] = a[0]; v[u + 4] = a[1]; v[u + 8] = a[2]; v[u + 12] = a[3];
    }
}

__device__ __forceinline__ float2 shflx1(float2 a) {
    return make_float2(__shfl_xor_sync(0xffffffffu, a.x, 1),
                       __shfl_xor_sync(0xffffffffu, a.y, 1));
}

// ---------------- K0: build twiddle tables ----------------
__global__ void k_init_tables() {
    int i = threadIdx.x;
    if (i < 64) {
        int r = i >> 3, u = i & 7;
        float s, c;
        sincospif(-2.0f * (float)(r * u) / 64.0f, &s, &c);
        g_t64[i] = make_float2(c, s);
    }
    if (i < 256) {
        int m = i >> 6, j = i & 63;
        float s, c;
        sincospif(-2.0f * (float)(m * j) / 256.0f, &s, &c);
        g_t256[i] = make_float2(c, s);
    }
}

// ---------------- warp-level 512-pt forward FFT ----------------
__device__ __forceinline__ void wfft512_fwd(float2 v[16], float2* sw, int lane,
                                            float2 w512p, float2 w64p, float2 w32p) {
    dft16_dif<-1>(v);  // slot m <-> freq DR16(m)
    int lo = lane & 15, hib = (lane >> 4) << 3;
#pragma unroll
    for (int p = 0; p < 16; p++) sw[(lane << 4) + (p ^ lo ^ hib)] = v[DR16(p)];
    __syncwarp();
    int p = lane >> 1, h = lane & 1;
#pragma unroll
    for (int j = 0; j < 16; j++) v[j] = sw[((16 * h + j) << 4) + (p ^ j ^ (h << 3))];
    __syncwarp();
    {   // twiddle w512^{p*(16h+j)}: two 8-deep chains (j and j+8)
        float2 c0 = h ? w32p : make_float2(1.0f, 0.0f);
        float2 c1 = cmul(c0, w64p);
#pragma unroll
        for (int j = 0; j < 8; j++) {
            v[j] = cmul(v[j], c0);
            v[j + 8] = cmul(v[j + 8], c1);
            c0 = cmul(c0, w512p);
            c1 = cmul(c1, w512p);
        }
    }
    {   // radix-2 butterfly over halves; w32^j are literals
#pragma unroll
        for (int j = 0; j < 16; j++) {
            float2 other = shflx1(v[j]);
            if (h == 0) v[j] = cadd(v[j], other);
            else if (j == 0) v[j] = csub(other, v[j]);
            else v[j] = cmul(csub(other, v[j]), w32f(j));
        }
    }
    dft16_dif<-1>(v);  // slot m <-> q' = DR16(m)
}

// ---------------- K2f: filter spectrum in slot layout, scaled 1/N ----------------
__global__ __launch_bounds__(256, 4) void k_filter_spec(const float2* __restrict__ U,
                                                        float2* __restrict__ Fp) {
    __shared__ float2 sw[8][512];
    int lane = threadIdx.x & 31, w = threadIdx.x >> 5;
    int k1 = (blockIdx.x << 3) + w;
    int p = lane >> 1;
    float sA, cA, s6, c6, s0, c0;
    __sincosf(-(TWO_PI / 512.0f) * (float)p, &sA, &cA);
    __sincosf(-(TWO_PI / 64.0f) * (float)p, &s6, &c6);
    __sincosf(-(TWO_PI / 32.0f) * (float)p, &s0, &c0);
    const float2* u = U + (size_t)PAIRS * N_FFT + (k1 << 9);
    float2 v[16];
#pragma unroll
    for (int r = 0; r < 16; r++) v[r] = u[lane + 32 * r];
    wfft512_fwd(v, sw[w], lane, make_float2(cA, sA), make_float2(c6, s6), make_float2(c0, s0));
    float2* o = Fp + (k1 << 9) + (lane << 4);
#pragma unroll
    for (int m = 0; m < 16; m++)
        o[m] = make_float2(v[m].x * INV_N, v[m].y * INV_N);
}

// ---------------- K23: fwd FFT512 + multiply + inv FFT512 + w_N^{+n2 k1} ----------------
__global__ __launch_bounds__(256, 4) void k_stageB_conv(float2* U, const float4* __restrict__ Fp4) {
    __shared__ float2 sw[8][512];
    int lane = threadIdx.x & 31, w = threadIdx.x >> 5;
    int k1 = (blockIdx.x << 3) + w;
    int row = blockIdx.y;
    float2* u = U + (size_t)row * N_FFT + (k1 << 9);
    float2* s = sw[w];
    int p = lane >> 1, h = lane & 1;
    float sA, cA, s6, c6, s0, c0;
    __sincosf(-(TWO_PI / 512.0f) * (float)p, &sA, &cA);  // w512^p (fwd sign)
    __sincosf(-(TWO_PI / 64.0f) * (float)p, &s6, &c6);   // w64^p = w512^{8p}
    __sincosf(-(TWO_PI / 32.0f) * (float)p, &s0, &c0);   // w32^p = w512^{16p}
    float2 w512p = make_float2(cA, sA), w64p = make_float2(c6, s6), w32p = make_float2(c0, s0);

    float2 v[16];
#pragma unroll
    for (int r = 0; r < 16; r++) v[r] = u[lane + 32 * r];
    wfft512_fwd(v, s, lane, w512p, w64p, w32p);

    // multiply by filter spectrum (slot-aligned, 8 x LDG.128)
    const float4* Fr = Fp4 + (((k1 << 9) + (lane << 4)) >> 1);
#pragma unroll
    for (int m2 = 0; m2 < 8; m2++) {
        float4 f = __ldg(Fr + m2);
        v[2 * m2]     = cmul(v[2 * m2],     make_float2(f.x, f.y));
        v[2 * m2 + 1] = cmul(v[2 * m2 + 1], make_float2(f.z, f.w));
    }

    // ---- inverse ----
    dft16_dit<1>(v);  // digitrev in (slot m <-> q'=DR16(m)) -> NATURAL out: v[tau]
    {   // butterfly (w32^j literals) + conj twiddle, two 8-deep cB chains
        float2 cB0 = h ? w32p : make_float2(1.0f, 0.0f);
        float2 cB1 = cmul(cB0, w64p);
#pragma unroll
        for (int j = 0; j < 8; j++) {
            {
                float2 other = shflx1(v[j]);
                if (h == 0) v[j] = (j == 0) ? cadd(v[j], other) : cadd(v[j], cmulc(other, w32f(j)));
                else        v[j] = (j == 0) ? csub(other, v[j]) : csub(other, cmulc(v[j], w32f(j)));
                v[j] = cmulc(v[j], cB0);
                cB0 = cmul(cB0, w512p);
            }
            {
                int j8 = j + 8;
                float2 other = shflx1(v[j8]);
                if (h == 0) v[j8] = cadd(v[j8], cmulc(other, w32f(j8)));
                else        v[j8] = csub(other, cmulc(v[j8], w32f(j8)));
                v[j8] = cmulc(v[j8], cB1);
                cB1 = cmul(cB1, w512p);
            }
        }
    }
    __syncwarp();
#pragma unroll
    for (int j = 0; j < 16; j++) s[((j + 16 * h) << 4) + (p ^ j ^ (h << 3))] = v[j];
    __syncwarp();
    int lo = lane & 15, hib = (lane >> 4) << 3;
#pragma unroll
    for (int q = 0; q < 16; q++) v[q] = s[(lane << 4) + (q ^ lo ^ hib)];
    dft16_dif<1>(v);  // natural in -> slot m <-> r = DR16(m); n2 = lane + 32r

    // outer twiddle w_N^{+n2 k1}: two 8-deep chains (r and r+8)
    float sb, cb, ss, cs, s8, c8;
    __sincosf((TWO_PI / (float)N_FFT) * (float)(lane * k1), &sb, &cb);
    __sincosf((TWO_PI / 4096.0f) * (float)k1, &ss, &cs);  // w_N^{+32 k1}
    __sincosf((TWO_PI / 512.0f) * (float)k1, &s8, &c8);   // w_N^{+256 k1}
    float2 wk0 = make_float2(cb, sb), wstep = make_float2(cs, ss);
    float2 wk8 = cmul(wk0, make_float2(c8, s8));
#pragma unroll
    for (int r = 0; r < 8; r++) {
        u[lane + 32 * r] = cmul(v[DR16(r)], wk0);
        u[lane + 32 * (r + 8)] = cmul(v[DR16(r + 8)], wk8);
        wk0 = cmul(wk0, wstep);
        wk8 = cmul(wk8, wstep);
    }
}

// ---------------- K1: pack + FFT256 over n1 + w_N twiddle ----------------
__global__ __launch_bounds__(512) void k_stageA(const float* __restrict__ x,
                                                const float* __restrict__ filt,
                                                float2* __restrict__ U) {
    __shared__ float2 sm[256][16];
    int tx = threadIdx.x;
    int c = tx & 15, t = tx >> 4;
    int n2 = (blockIdx.x << 4) + c;
    int row = blockIdx.y;
    float2 v[8];
    if (row < PAIRS) {
        const float* xa = x + (size_t)row * T_LEN;
        const float* xb = x + (size_t)(row + PAIRS) * T_LEN;
#pragma unroll
        for (int r = 0; r < 4; r++) {
            int n = ((t + 32 * r) << 9) + n2;
            v[r] = make_float2(__ldg(xa + n), __ldg(xb + n));
        }
    } else {
#pragma unroll
        for (int r = 0; r < 4; r++) {
            int n = ((t + 32 * r) << 9) + n2;
            v[r] = make_float2(__ldg(filt + n), 0.0f);
        }
    }
#pragma unroll
    for (int r = 4; r < 8; r++) v[r] = make_float2(0.0f, 0.0f);

    dft8<-1>(v);
#pragma unroll
    for (int r = 0; r < 8; r++) sm[8 * t + r][c] = v[r];
    __syncthreads();
#pragma unroll
    for (int r = 0; r < 8; r++) v[r] = sm[t + 32 * r][c];
    {
        int t8 = t & 7;
#pragma unroll
        for (int r = 1; r < 8; r++) v[r] = cmul(v[r], __ldg(&g_t64[r * 8 + t8]));
    }
    dft8<-1>(v);
    __syncthreads();
    {
        int base = ((t >> 3) << 6) + (t & 7);
#pragma unroll
        for (int r = 0; r < 8; r++) sm[base + 8 * r][c] = v[r];
    }
    __syncthreads();

    float s64, c64;
    __sincosf(-(TWO_PI / 2048.0f) * (float)n2, &s64, &c64);
    float2 w64 = make_float2(c64, s64);
    float2* Ur = U + (size_t)row * N_FFT;
#pragma unroll
    for (int g = 0; g < 2; g++) {
        int j = t + 32 * g;
        float2 q[4];
#pragma unroll
        for (int m = 0; m < 4; m++) q[m] = sm[j + 64 * m][c];
#pragma unroll
        for (int m = 1; m < 4; m++) q[m] = cmul(q[m], __ldg(&g_t256[m * 64 + j]));
        dft4<-1>(q);
        float sb, cb;
        __sincosf(-(TWO_PI / (float)N_FFT) * (float)(n2 * j), &sb, &cb);
        float2 wk = make_float2(cb, sb);
#pragma unroll
        for (int m = 0; m < 4; m++) {
            int k1 = j + 64 * m;
            Ur[(k1 << 9) + n2] = cmul(q[m], wk);
            wk = cmul(wk, w64);
        }
    }
}

// ---------------- K4: IFFT256 over k1 + causal unpack ----------------
__global__ __launch_bounds__(512) void k_stageAinv(const float2* __restrict__ U,
                                                   float* __restrict__ y) {
    __shared__ float2 sm[256][16];
    int tx = threadIdx.x;
    int c = tx & 15, t = tx >> 4;
    int n2 = (blockIdx.x << 4) + c;
    int row = blockIdx.y;
    const float2* u = U + (size_t)row * N_FFT + n2;
    float2 v[8];
#pragma unroll
    for (int r = 0; r < 8; r++) v[r] = __ldg(u + (size_t)((t + 32 * r) << 9));
    dft8<1>(v);
#pragma unroll
    for (int r = 0; r < 8; r++) sm[8 * t + r][c] = v[r];
    __syncthreads();
#pragma unroll
    for (int r = 0; r < 8; r++) v[r] = sm[t + 32 * r][c];
    {
        int t8 = t & 7;
#pragma unroll
        for (int r = 1; r < 8; r++) v[r] = cmulc(v[r], __ldg(&g_t64[r * 8 + t8]));
    }
    dft8<1>(v);
    __syncthreads();
    {
        int base = ((t >> 3) << 6) + (t & 7);
#pragma unroll
        for (int r = 0; r < 8; r++) sm[base + 8 * r][c] = v[r];
    }
    __syncthreads();

    float* ya = y + (size_t)row * T_LEN;
    float* yb = y + (size_t)(row + PAIRS) * T_LEN;
#pragma unroll
    for (int g = 0; g < 2; g++) {
        int j = t + 32 * g;
        float2 q[4];
#pragma unroll
        for (int m = 0; m < 4; m++) q[m] = sm[j + 64 * m][c];
#pragma unroll
        for (int m = 1; m < 4; m++) q[m] = cmulc(q[m], __ldg(&g_t256[m * 64 + j]));
        dft4<1>(q);
#pragma unroll
        for (int m = 0; m < 2; m++) {
            int n = ((j + 64 * m) << 9) + n2;
            ya[n] = q[m].x;
            yb[n] = q[m].y;
        }
    }
}

extern "C" void kernel_launch(void* const* d_in, const int* in_sizes, int n_in,
                              void* d_out, int out_size) {
    const float* x = (const float*)d_in[0];
    const float* filt = (const float*)d_in[1];
    float* y = (float*)d_out;

    float2* U = nullptr;
    float4* F4 = nullptr;
    cudaGetSymbolAddress((void**)&U, g_buf);
    cudaGetSymbolAddress((void**)&F4, g_fspec4);

    k_init_tables<<<1, 512>>>();
    k_stageA<<<dim3(32, ROWS_F), 512>>>(x, filt, U);
    k_filter_spec<<<32, 256>>>(U, (float2*)F4);
    k_stageB_conv<<<dim3(32, PAIRS), 256>>>(U, F4);
    k_stageAinv<<<dim3(32, PAIRS), 512>>>(U, y);
}

// round 12
// speedup vs baseline: 1.0284x; 1.0284x over previous
#include <cuda_runtime.h>

// EpochedFutureFill == causal FIR conv, B=256, T=L=65536, via FFT of N=131072.
// Four-step decomposition: N = 256 (n1, stride 512) x 512 (n2, contiguous).
//   K0 : build twiddle tables (K1 only)
//   K1 : pack + FFT256 over n1 (strided) + w_N^{-n2 k1}  -> U[k1][n2]
//   K2f: filter row: warp-FFT512 -> F (slot layout, scaled 1/N)
//   K23: warp-autonomous FFT512 fwd + multiply + IFFT512 + w_N^{+n2 k1} (in place)
//   K4 : IFFT256 over k1 as 16x16 (one swizzled smem transpose) + causal unpack
// R12: K4 restructured to 16-pt in-thread DFTs with a single conflict-free
// transpose (2 smem ops/point instead of 4, one barrier instead of three).

namespace {
constexpr int N_FFT = 131072;
constexpr int T_LEN = 65536;
constexpr int PAIRS = 128;
constexpr int ROWS_F = 129;
constexpr float TWO_PI = 6.28318530717958647692f;
constexpr float INV_N = 1.0f / (float)N_FFT;
}

// digit-reverse for radix-4^2 of 16: slot(p) = ((p&3)<<2)|(p>>2)  (involution)
#define DR16(p) ((((p) & 3) << 2) | ((p) >> 2))

// Scratch (no cudaMalloc allowed).
__device__ float2 g_buf[(size_t)ROWS_F * N_FFT];
__device__ float4 g_fspec4[N_FFT / 2];  // F in per-lane-contiguous slot layout
__device__ float2 g_t64[8 * 8];
__device__ float2 g_t256[4 * 64];

__device__ __forceinline__ float2 cadd(float2 a, float2 b) { return make_float2(a.x + b.x, a.y + b.y); }
__device__ __forceinline__ float2 csub(float2 a, float2 b) { return make_float2(a.x - b.x, a.y - b.y); }
__device__ __forceinline__ float2 cmul(float2 a, float2 b) {
    return make_float2(fmaf(a.x, b.x, -a.y * b.y), fmaf(a.x, b.y, a.y * b.x));
}
__device__ __forceinline__ float2 cmulc(float2 a, float2 b) {  // a * conj(b)
    return make_float2(fmaf(a.x, b.x, a.y * b.y), fmaf(a.y, b.x, -a.x * b.y));
}
template <int DIR>
__device__ __forceinline__ float2 cmuli(float2 a) {  // * (i*DIR)
    return (DIR < 0) ? make_float2(a.y, -a.x) : make_float2(-a.y, a.x);
}

// exp(-2*pi*i*j/32), compile-time after unrolling -> FFMA-imm operands.
__device__ __forceinline__ float2 w32f(int j) {
    switch (j & 15) {
        case 0:  return make_float2(1.0f, 0.0f);
        case 1:  return make_float2(0.9807852804032304f, -0.19509032201612827f);
        case 2:  return make_float2(0.9238795325112868f, -0.3826834323650898f);
        case 3:  return make_float2(0.8314696123025452f, -0.5555702330196022f);
        case 4:  return make_float2(0.7071067811865476f, -0.7071067811865476f);
        case 5:  return make_float2(0.5555702330196022f, -0.8314696123025452f);
        case 6:  return make_float2(0.3826834323650898f, -0.9238795325112868f);
        case 7:  return make_float2(0.19509032201612827f, -0.9807852804032304f);
        case 8:  return make_float2(0.0f, -1.0f);
        case 9:  return make_float2(-0.19509032201612827f, -0.9807852804032304f);
        case 10: return make_float2(-0.3826834323650898f, -0.9238795325112868f);
        case 11: return make_float2(-0.5555702330196022f, -0.8314696123025452f);
        case 12: return make_float2(-0.7071067811865476f, -0.7071067811865476f);
        case 13: return make_float2(-0.8314696123025452f, -0.5555702330196022f);
        case 14: return make_float2(-0.9238795325112868f, -0.3826834323650898f);
        default: return make_float2(-0.9807852804032304f, -0.19509032201612827f);
    }
}

template <int DIR>
__device__ __forceinline__ void dft4(float2 v[4]) {
    float2 t0 = cadd(v[0], v[2]);
    float2 t1 = cadd(v[1], v[3]);
    float2 t2 = csub(v[0], v[2]);
    float2 d  = csub(v[1], v[3]);
    v[0] = cadd(t0, t1);
    v[2] = csub(t0, t1);
    if (DIR < 0) {
        v[1] = make_float2(t2.x + d.y, t2.y - d.x);
        v[3] = make_float2(t2.x - d.y, t2.y + d.x);
    } else {
        v[1] = make_float2(t2.x - d.y, t2.y + d.x);
        v[3] = make_float2(t2.x + d.y, t2.y - d.x);
    }
}

template <int DIR>
__device__ __forceinline__ void dft8(float2 v[8]) {
    const float C = 0.70710678118654752440f;
    float2 b[4], d[4];
#pragma unroll
    for (int i = 0; i < 4; i++) {
        b[i] = cadd(v[i], v[i + 4]);
        d[i] = csub(v[i], v[i + 4]);
    }
    d[1] = cmul(d[1], make_float2(C, (float)DIR * C));
    d[2] = cmuli<DIR>(d[2]);
    d[3] = cmul(d[3], make_float2(-C, (float)DIR * C));
    dft4<DIR>(b);
    dft4<DIR>(d);
    v[0] = b[0]; v[2] = b[1]; v[4] = b[2]; v[6] = b[3];
    v[1] = d[0]; v[3] = d[1]; v[5] = d[2]; v[7] = d[3];
}

// In-place DIF radix-4^2 16-pt DFT. Input natural; output: slot m holds X[DR16(m)].
template <int DIR>
__device__ __forceinline__ void dft16_dif(float2 v[16]) {
    const float C1 = 0.92387953251128674f, S1 = 0.38268343236508978f;
    const float C2 = 0.70710678118654752f;
    const float D = (float)DIR;
    const float2 w1 = make_float2(C1, D * S1), w2 = make_float2(C2, D * C2);
    const float2 w3 = make_float2(S1, D * C1), w6 = make_float2(-C2, D * C2);
    const float2 w9 = make_float2(-C1, -D * S1);
#pragma unroll
    for (int j = 0; j < 4; j++) {
        float2 a[4] = {v[j], v[j + 4], v[j + 8], v[j + 12]};
        dft4<DIR>(a);
        if (j == 1) { a[1] = cmul(a[1], w1); a[2] = cmul(a[2], w2); a[3] = cmul(a[3], w3); }
        else if (j == 2) { a[1] = cmul(a[1], w2); a[2] = cmuli<DIR>(a[2]); a[3] = cmul(a[3], w6); }
        else if (j == 3) { a[1] = cmul(a[1], w3); a[2] = cmul(a[2], w6); a[3] = cmul(a[3], w9); }
        v[j] = a[0]; v[j + 4] = a[1]; v[j + 8] = a[2]; v[j + 12] = a[3];
    }
#pragma unroll
    for (int q = 0; q < 4; q++) {
        float2 a[4] = {v[4 * q], v[4 * q + 1], v[4 * q + 2], v[4 * q + 3]};
        dft4<DIR>(a);
        v[4 * q] = a[0]; v[4 * q + 1] = a[1]; v[4 * q + 2] = a[2]; v[4 * q + 3] = a[3];
    }
}

// In-place DIT radix-4^2 16-pt DFT. Input: slot m holds in[DR16(m)]. Output NATURAL.
template <int DIR>
__device__ __forceinline__ void dft16_dit(float2 v[16]) {
    const float C1 = 0.92387953251128674f, S1 = 0.38268343236508978f;
    const float C2 = 0.70710678118654752f;
    const float D = (float)DIR;
    const float2 w1 = make_float2(C1, D * S1), w2 = make_float2(C2, D * C2);
    const float2 w3 = make_float2(S1, D * C1), w6 = make_float2(-C2, D * C2);
    const float2 w9 = make_float2(-C1, -D * S1);
#pragma unroll
    for (int q = 0; q < 4; q++) {
        float2 a[4] = {v[4 * q], v[4 * q + 1], v[4 * q + 2], v[4 * q + 3]};
        dft4<DIR>(a);
        if (q == 1) { a[1] = cmul(a[1], w1); a[2] = cmul(a[2], w2); a[3] = cmul(a[3], w3); }
        else if (q == 2) { a[1] = cmul(a[1], w2); a[2] = cmuli<DIR>(a[2]); a[3] = cmul(a[3], w6); }
        else if (q == 3) { a[1] = cmul(a[1], w3); a[2] = cmul(a[2], w6); a[3] = cmul(a[3], w9); }
        v[4 * q] = a[0]; v[4 * q + 1] = a[1]; v[4 * q + 2] = a[2]; v[4 * q + 3] = a[3];
    }
#pragma unroll
    for (int u = 0; u < 4; u++) {
        float2 a[4] = {v[u], v[u + 4], v[u + 8], v[u + 12]};
        dft4<DIR>(a);
        v[u] = a[0]; v[u + 4] = a[1]; v[u + 8] = a[2]; v[u + 12] = a[3];
    }
}

__device__ __forceinline__ float2 shflx1(float2 a) {
    return make_float2(__shfl_xor_sync(0xffffffffu, a.x, 1),
                       __shfl_xor_sync(0xffffffffu, a.y, 1));
}

// ---------------- K0: build twiddle tables ----------------
__global__ void k_init_tables() {
    int i = threadIdx.x;
    if (i < 64) {
        int r = i >> 3, u = i & 7;
        float s, c;
        sincospif(-2.0f * (float)(r * u) / 64.0f, &s, &c);
        g_t64[i] = make_float2(c, s);
    }
    if (i < 256) {
        int m = i >> 6, j = i & 63;
        float s, c;
        sincospif(-2.0f * (float)(m * j) / 256.0f, &s, &c);
        g_t256[i] = make_float2(c, s);
    }
}

// ---------------- warp-level 512-pt forward FFT ----------------
__device__ __forceinline__ void wfft512_fwd(float2 v[16], float2* sw, int lane,
                                            float2 w512p, float2 w64p, float2 w32p) {
    dft16_dif<-1>(v);  // slot m <-> freq DR16(m)
    int lo = lane & 15, hib = (lane >> 4) << 3;
#pragma unroll
    for (int p = 0; p < 16; p++) sw[(lane << 4) + (p ^ lo ^ hib)] = v[DR16(p)];
    __syncwarp();
    int p = lane >> 1, h = lane & 1;
#pragma unroll
    for (int j = 0; j < 16; j++) v[j] = sw[((16 * h + j) << 4) + (p ^ j ^ (h << 3))];
    __syncwarp();
    {   // twiddle w512^{p*(16h+j)}: two 8-deep chains (j and j+8)
        float2 c0 = h ? w32p : make_float2(1.0f, 0.0f);
        float2 c1 = cmul(c0, w64p);
#pragma unroll
        for (int j = 0; j < 8; j++) {
            v[j] = cmul(v[j], c0);
            v[j + 8] = cmul(v[j + 8], c1);
            c0 = cmul(c0, w512p);
            c1 = cmul(c1, w512p);
        }
    }
    {   // radix-2 butterfly over halves; w32^j are literals
#pragma unroll
        for (int j = 0; j < 16; j++) {
            float2 other = shflx1(v[j]);
            if (h == 0) v[j] = cadd(v[j], other);
            else if (j == 0) v[j] = csub(other, v[j]);
            else v[j] = cmul(csub(other, v[j]), w32f(j));
        }
    }
    dft16_dif<-1>(v);  // slot m <-> q' = DR16(m)
}

// ---------------- K2f: filter spectrum in slot layout, scaled 1/N ----------------
__global__ __launch_bounds__(256, 4) void k_filter_spec(const float2* __restrict__ U,
                                                        float2* __restrict__ Fp) {
    __shared__ float2 sw[8][512];
    int lane = threadIdx.x & 31, w = threadIdx.x >> 5;
    int k1 = (blockIdx.x << 3) + w;
    int p = lane >> 1;
    float sA, cA, s6, c6, s0, c0;
    __sincosf(-(TWO_PI / 512.0f) * (float)p, &sA, &cA);
    __sincosf(-(TWO_PI / 64.0f) * (float)p, &s6, &c6);
    __sincosf(-(TWO_PI / 32.0f) * (float)p, &s0, &c0);
    const float2* u = U + (size_t)PAIRS * N_FFT + (k1 << 9);
    float2 v[16];
#pragma unroll
    for (int r = 0; r < 16; r++) v[r] = u[lane + 32 * r];
    wfft512_fwd(v, sw[w], lane, make_float2(cA, sA), make_float2(c6, s6), make_float2(c0, s0));
    float2* o = Fp + (k1 << 9) + (lane << 4);
#pragma unroll
    for (int m = 0; m < 16; m++)
        o[m] = make_float2(v[m].x * INV_N, v[m].y * INV_N);
}

// ---------------- K23: fwd FFT512 + multiply + inv FFT512 + w_N^{+n2 k1} ----------------
__global__ __launch_bounds__(256, 4) void k_stageB_conv(float2* U, const float4* __restrict__ Fp4) {
    __shared__ float2 sw[8][512];
    int lane = threadIdx.x & 31, w = threadIdx.x >> 5;
    int k1 = (blockIdx.x << 3) + w;
    int row = blockIdx.y;
    float2* u = U + (size_t)row * N_FFT + (k1 << 9);
    float2* s = sw[w];
    int p = lane >> 1, h = lane & 1;
    float sA, cA, s6, c6, s0, c0;
    __sincosf(-(TWO_PI / 512.0f) * (float)p, &sA, &cA);  // w512^p (fwd sign)
    __sincosf(-(TWO_PI / 64.0f) * (float)p, &s6, &c6);   // w64^p = w512^{8p}
    __sincosf(-(TWO_PI / 32.0f) * (float)p, &s0, &c0);   // w32^p = w512^{16p}
    float2 w512p = make_float2(cA, sA), w64p = make_float2(c6, s6), w32p = make_float2(c0, s0);

    float2 v[16];
#pragma unroll
    for (int r = 0; r < 16; r++) v[r] = u[lane + 32 * r];
    wfft512_fwd(v, s, lane, w512p, w64p, w32p);

    // multiply by filter spectrum (slot-aligned, 8 x LDG.128)
    const float4* Fr = Fp4 + (((k1 << 9) + (lane << 4)) >> 1);
#pragma unroll
    for (int m2 = 0; m2 < 8; m2++) {
        float4 f = __ldg(Fr + m2);
        v[2 * m2]     = cmul(v[2 * m2],     make_float2(f.x, f.y));
        v[2 * m2 + 1] = cmul(v[2 * m2 + 1], make_float2(f.z, f.w));
    }

    // ---- inverse ----
    dft16_dit<1>(v);  // digitrev in (slot m <-> q'=DR16(m)) -> NATURAL out: v[tau]
    {   // butterfly (w32^j literals) + conj twiddle, two 8-deep cB chains
        float2 cB0 = h ? w32p : make_float2(1.0f, 0.0f);
        float2 cB1 = cmul(cB0, w64p);
#pragma unroll
        for (int j = 0; j < 8; j++) {
            {
                float2 other = shflx1(v[j]);
                if (h == 0) v[j] = (j == 0) ? cadd(v[j], other) : cadd(v[j], cmulc(other, w32f(j)));
                else        v[j] = (j == 0) ? csub(other, v[j]) : csub(other, cmulc(v[j], w32f(j)));
                v[j] = cmulc(v[j], cB0);
                cB0 = cmul(cB0, w512p);
            }
            {
                int j8 = j + 8;
                float2 other = shflx1(v[j8]);
                if (h == 0) v[j8] = cadd(v[j8], cmulc(other, w32f(j8)));
                else        v[j8] = csub(other, cmulc(v[j8], w32f(j8)));
                v[j8] = cmulc(v[j8], cB1);
                cB1 = cmul(cB1, w512p);
            }
        }
    }
    __syncwarp();
#pragma unroll
    for (int j = 0; j < 16; j++) s[((j + 16 * h) << 4) + (p ^ j ^ (h << 3))] = v[j];
    __syncwarp();
    int lo = lane & 15, hib = (lane >> 4) << 3;
#pragma unroll
    for (int q = 0; q < 16; q++) v[q] = s[(lane << 4) + (q ^ lo ^ hib)];
    dft16_dif<1>(v);  // natural in -> slot m <-> r = DR16(m); n2 = lane + 32r

    // outer twiddle w_N^{+n2 k1}: two 8-deep chains (r and r+8)
    float sb, cb, ss, cs, s8, c8;
    __sincosf((TWO_PI / (float)N_FFT) * (float)(lane * k1), &sb, &cb);
    __sincosf((TWO_PI / 4096.0f) * (float)k1, &ss, &cs);  // w_N^{+32 k1}
    __sincosf((TWO_PI / 512.0f) * (float)k1, &s8, &c8);   // w_N^{+256 k1}
    float2 wk0 = make_float2(cb, sb), wstep = make_float2(cs, ss);
    float2 wk8 = cmul(wk0, make_float2(c8, s8));
#pragma unroll
    for (int r = 0; r < 8; r++) {
        u[lane + 32 * r] = cmul(v[DR16(r)], wk0);
        u[lane + 32 * (r + 8)] = cmul(v[DR16(r + 8)], wk8);
        wk0 = cmul(wk0, wstep);
        wk8 = cmul(wk8, wstep);
    }
}

// ---------------- K1: pack + FFT256 over n1 + w_N twiddle ----------------
__global__ __launch_bounds__(512) void k_stageA(const float* __restrict__ x,
                                                const float* __restrict__ filt,
                                                float2* __restrict__ U) {
    __shared__ float2 sm[256][16];
    int tx = threadIdx.x;
    int c = tx & 15, t = tx >> 4;
    int n2 = (blockIdx.x << 4) + c;
    int row = blockIdx.y;
    float2 v[8];
    if (row < PAIRS) {
        const float* xa = x + (size_t)row * T_LEN;
        const float* xb = x + (size_t)(row + PAIRS) * T_LEN;
#pragma unroll
        for (int r = 0; r < 4; r++) {
            int n = ((t + 32 * r) << 9) + n2;
            v[r] = make_float2(__ldg(xa + n), __ldg(xb + n));
        }
    } else {
#pragma unroll
        for (int r = 0; r < 4; r++) {
            int n = ((t + 32 * r) << 9) + n2;
            v[r] = make_float2(__ldg(filt + n), 0.0f);
        }
    }
#pragma unroll
    for (int r = 4; r < 8; r++) v[r] = make_float2(0.0f, 0.0f);

    dft8<-1>(v);
#pragma unroll
    for (int r = 0; r < 8; r++) sm[8 * t + r][c] = v[r];
    __syncthreads();
#pragma unroll
    for (int r = 0; r < 8; r++) v[r] = sm[t + 32 * r][c];
    {
        int t8 = t & 7;
#pragma unroll
        for (int r = 1; r < 8; r++) v[r] = cmul(v[r], __ldg(&g_t64[r * 8 + t8]));
    }
    dft8<-1>(v);
    __syncthreads();
    {
        int base = ((t >> 3) << 6) + (t & 7);
#pragma unroll
        for (int r = 0; r < 8; r++) sm[base + 8 * r][c] = v[r];
    }
    __syncthreads();

    float s64, c64;
    __sincosf(-(TWO_PI / 2048.0f) * (float)n2, &s64, &c64);
    float2 w64 = make_float2(c64, s64);
    float2* Ur = U + (size_t)row * N_FFT;
#pragma unroll
    for (int g = 0; g < 2; g++) {
        int j = t + 32 * g;
        float2 q[4];
#pragma unroll
        for (int m = 0; m < 4; m++) q[m] = sm[j + 64 * m][c];
#pragma unroll
        for (int m = 1; m < 4; m++) q[m] = cmul(q[m], __ldg(&g_t256[m * 64 + j]));
        dft4<-1>(q);
        float sb, cb;
        __sincosf(-(TWO_PI / (float)N_FFT) * (float)(n2 * j), &sb, &cb);
        float2 wk = make_float2(cb, sb);
#pragma unroll
        for (int m = 0; m < 4; m++) {
            int k1 = j + 64 * m;
            Ur[(k1 << 9) + n2] = cmul(q[m], wk);
            wk = cmul(wk, w64);
        }
    }
}

// ---------------- K4: IFFT256 over k1 (16x16, one transpose) + causal unpack --------
// Block 256 = 16 t (FFT lanes) x 16 c (n2 columns). grid (32, 128).
// x[n1] = sum_k1 U[k1] e^{+2pi i n1 k1/256}; k1 = t + 16s, n1 = ni + 16no.
// inner dft16 over s -> ni; twiddle w256^{+ni t}; transpose; outer dft16 over t -> no.
// Keep n1 < 128 -> no < 8.
__global__ __launch_bounds__(256, 4) void k_stageAinv(const float2* __restrict__ U,
                                                      float* __restrict__ y) {
    __shared__ float2 sm[16][16][16];  // [t][ni][swizzled c]
    int tx = threadIdx.x;
    int c = tx & 15, t = tx >> 4;
    int n2 = (blockIdx.x << 4) + c;
    int row = blockIdx.y;
    const float2* u = U + (size_t)row * N_FFT + n2;
    float2 v[16];
#pragma unroll
    for (int s = 0; s < 16; s++) v[s] = __ldg(u + (size_t)((t + 16 * s) << 9));
    dft16_dif<1>(v);  // inverse inner over s: slot m <-> ni = DR16(m)
    {   // twiddle w256^{+ni t}: two 8-deep chains over natural ni
        float sA, cA, s8, c8;
        __sincosf(-(TWO_PI / 256.0f) * (float)t, &sA, &cA);  // w256^{t} (fwd sign)
        __sincosf(-(TWO_PI / 32.0f) * (float)t, &s8, &c8);   // w256^{8t} = w32^{t}
        float2 step = make_float2(cA, sA);
        float2 c0 = make_float2(1.0f, 0.0f);
        float2 c1 = make_float2(c8, s8);
#pragma unroll
        for (int ni = 0; ni < 8; ni++) {
            v[DR16(ni)] = cmulc(v[DR16(ni)], c0);          // * w256^{+ni t}
            v[DR16(ni + 8)] = cmulc(v[DR16(ni + 8)], c1);  // * w256^{+(ni+8) t}
            c0 = cmul(c0, step);
            c1 = cmul(c1, step);
        }
    }
    // transpose: sm[t][ni][swz]; swizzle breaks both t-parity (store) and
    // ni-parity (gather) bank collisions.
#pragma unroll
    for (int ni = 0; ni < 16; ni++)
        sm[t][ni][(c + 8 * ((t + ni) & 1)) & 15] = v[DR16(ni)];
    __syncthreads();
#pragma unroll
    for (int tt = 0; tt < 16; tt++)
        v[tt] = sm[tt][t][(c + 8 * ((tt + t) & 1)) & 15];
    dft16_dif<1>(v);  // inverse outer over t: slot m <-> no = DR16(m)

    float* ya = y + (size_t)row * T_LEN;
    float* yb = y + (size_t)(row + PAIRS) * T_LEN;
#pragma unroll
    for (int no = 0; no < 8; no++) {  // n1 = t + 16*no < 128
        int n = ((t + 16 * no) << 9) + n2;
        float2 q = v[DR16(no)];
        ya[n] = q.x;
        yb[n] = q.y;
    }
}

extern "C" void kernel_launch(void* const* d_in, const int* in_sizes, int n_in,
                              void* d_out, int out_size) {
    const float* x = (const float*)d_in[0];
    const float* filt = (const float*)d_in[1];
    float* y = (float*)d_out;

    float2* U = nullptr;
    float4* F4 = nullptr;
    cudaGetSymbolAddress((void**)&U, g_buf);
    cudaGetSymbolAddress((void**)&F4, g_fspec4);

    k_init_tables<<<1, 512>>>();
    k_stageA<<<dim3(32, ROWS_F), 512>>>(x, filt, U);
    k_filter_spec<<<32, 256>>>(U, (float2*)F4);
    k_stageB_conv<<<dim3(32, PAIRS), 256>>>(U, F4);
    k_stageAinv<<<dim3(32, PAIRS), 256>>>(U, y);
}

// round 13
// speedup vs baseline: 1.0808x; 1.0509x over previous
#include <cuda_runtime.h>

// EpochedFutureFill == causal FIR conv, B=256, T=L=65536, via FFT of N=131072.
// Four-step decomposition: N = 256 (n1, stride 512) x 512 (n2, contiguous).
//   K1 : pack + FFT256 over n1 (16x16, one transpose, zero-half aware) + w_N twiddle
//   K2f: filter row: warp-FFT512 -> F (slot layout, scaled 1/N)
//   K23: warp-autonomous FFT512 fwd + multiply + IFFT512 + w_N^{+n2 k1} (in place)
//   K4 : IFFT256 over k1 (16x16, one transpose) + causal unpack
// R13: K1 rewritten like K4 (single swizzled transpose, computed twiddle chains,
// dft16_dif_z8 exploiting the zero-padded upper half). No twiddle tables left.

namespace {
constexpr int N_FFT = 131072;
constexpr int T_LEN = 65536;
constexpr int PAIRS = 128;
constexpr int ROWS_F = 129;
constexpr float TWO_PI = 6.28318530717958647692f;
constexpr float INV_N = 1.0f / (float)N_FFT;
}

// digit-reverse for radix-4^2 of 16: slot(p) = ((p&3)<<2)|(p>>2)  (involution)
#define DR16(p) ((((p) & 3) << 2) | ((p) >> 2))

// Scratch (no cudaMalloc allowed).
__device__ float2 g_buf[(size_t)ROWS_F * N_FFT];
__device__ float4 g_fspec4[N_FFT / 2];  // F in per-lane-contiguous slot layout

__device__ __forceinline__ float2 cadd(float2 a, float2 b) { return make_float2(a.x + b.x, a.y + b.y); }
__device__ __forceinline__ float2 csub(float2 a, float2 b) { return make_float2(a.x - b.x, a.y - b.y); }
__device__ __forceinline__ float2 cmul(float2 a, float2 b) {
    return make_float2(fmaf(a.x, b.x, -a.y * b.y), fmaf(a.x, b.y, a.y * b.x));
}
__device__ __forceinline__ float2 cmulc(float2 a, float2 b) {  // a * conj(b)
    return make_float2(fmaf(a.x, b.x, a.y * b.y), fmaf(a.y, b.x, -a.x * b.y));
}
template <int DIR>
__device__ __forceinline__ float2 cmuli(float2 a) {  // * (i*DIR)
    return (DIR < 0) ? make_float2(a.y, -a.x) : make_float2(-a.y, a.x);
}

// exp(-2*pi*i*j/32), compile-time after unrolling -> FFMA-imm operands.
__device__ __forceinline__ float2 w32f(int j) {
    switch (j & 15) {
        case 0:  return make_float2(1.0f, 0.0f);
        case 1:  return make_float2(0.9807852804032304f, -0.19509032201612827f);
        case 2:  return make_float2(0.9238795325112868f, -0.3826834323650898f);
        case 3:  return make_float2(0.8314696123025452f, -0.5555702330196022f);
        case 4:  return make_float2(0.7071067811865476f, -0.7071067811865476f);
        case 5:  return make_float2(0.5555702330196022f, -0.8314696123025452f);
        case 6:  return make_float2(0.3826834323650898f, -0.9238795325112868f);
        case 7:  return make_float2(0.19509032201612827f, -0.9807852804032304f);
        case 8:  return make_float2(0.0f, -1.0f);
        case 9:  return make_float2(-0.19509032201612827f, -0.9807852804032304f);
        case 10: return make_float2(-0.3826834323650898f, -0.9238795325112868f);
        case 11: return make_float2(-0.5555702330196022f, -0.8314696123025452f);
        case 12: return make_float2(-0.7071067811865476f, -0.7071067811865476f);
        case 13: return make_float2(-0.8314696123025452f, -0.5555702330196022f);
        case 14: return make_float2(-0.9238795325112868f, -0.3826834323650898f);
        default: return make_float2(-0.9807852804032304f, -0.19509032201612827f);
    }
}

template <int DIR>
__device__ __forceinline__ void dft4(float2 v[4]) {
    float2 t0 = cadd(v[0], v[2]);
    float2 t1 = cadd(v[1], v[3]);
    float2 t2 = csub(v[0], v[2]);
    float2 d  = csub(v[1], v[3]);
    v[0] = cadd(t0, t1);
    v[2] = csub(t0, t1);
    if (DIR < 0) {
        v[1] = make_float2(t2.x + d.y, t2.y - d.x);
        v[3] = make_float2(t2.x - d.y, t2.y + d.x);
    } else {
        v[1] = make_float2(t2.x - d.y, t2.y + d.x);
        v[3] = make_float2(t2.x + d.y, t2.y - d.x);
    }
}

// Shared twiddle block for the dft16 variants (applied to a[] after level-1 dft4, row j).
template <int DIR>
__device__ __forceinline__ void dft16_l1_twiddle(float2 a[4], int j) {
    const float C1 = 0.92387953251128674f, S1 = 0.38268343236508978f;
    const float C2 = 0.70710678118654752f;
    const float D = (float)DIR;
    const float2 w1 = make_float2(C1, D * S1), w2 = make_float2(C2, D * C2);
    const float2 w3 = make_float2(S1, D * C1), w6 = make_float2(-C2, D * C2);
    const float2 w9 = make_float2(-C1, -D * S1);
    if (j == 1) { a[1] = cmul(a[1], w1); a[2] = cmul(a[2], w2); a[3] = cmul(a[3], w3); }
    else if (j == 2) { a[1] = cmul(a[1], w2); a[2] = cmuli<DIR>(a[2]); a[3] = cmul(a[3], w6); }
    else if (j == 3) { a[1] = cmul(a[1], w3); a[2] = cmul(a[2], w6); a[3] = cmul(a[3], w9); }
}

// In-place DIF radix-4^2 16-pt DFT. Input natural; output: slot m holds X[DR16(m)].
template <int DIR>
__device__ __forceinline__ void dft16_dif(float2 v[16]) {
#pragma unroll
    for (int j = 0; j < 4; j++) {
        float2 a[4] = {v[j], v[j + 4], v[j + 8], v[j + 12]};
        dft4<DIR>(a);
        dft16_l1_twiddle<DIR>(a, j);
        v[j] = a[0]; v[j + 4] = a[1]; v[j + 8] = a[2]; v[j + 12] = a[3];
    }
#pragma unroll
    for (int q = 0; q < 4; q++) {
        float2 a[4] = {v[4 * q], v[4 * q + 1], v[4 * q + 2], v[4 * q + 3]};
        dft4<DIR>(a);
        v[4 * q] = a[0]; v[4 * q + 1] = a[1]; v[4 * q + 2] = a[2]; v[4 * q + 3] = a[3];
    }
}

// DIF 16-pt DFT with inputs 8..15 known zero (only v[0..7] read). Output as dft16_dif.
template <int DIR>
__device__ __forceinline__ void dft16_dif_z8(float2 v[16]) {
#pragma unroll
    for (int j = 0; j < 4; j++) {
        float2 in0 = v[j], in1 = v[j + 4];
        float2 a[4];
        a[0] = cadd(in0, in1);
        a[2] = csub(in0, in1);
        if (DIR < 0) {
            a[1] = make_float2(in0.x + in1.y, in0.y - in1.x);
            a[3] = make_float2(in0.x - in1.y, in0.y + in1.x);
        } else {
            a[1] = make_float2(in0.x - in1.y, in0.y + in1.x);
            a[3] = make_float2(in0.x + in1.y, in0.y - in1.x);
        }
        dft16_l1_twiddle<DIR>(a, j);
        v[j] = a[0]; v[j + 4] = a[1]; v[j + 8] = a[2]; v[j + 12] = a[3];
    }
#pragma unroll
    for (int q = 0; q < 4; q++) {
        float2 a[4] = {v[4 * q], v[4 * q + 1], v[4 * q + 2], v[4 * q + 3]};
        dft4<DIR>(a);
        v[4 * q] = a[0]; v[4 * q + 1] = a[1]; v[4 * q + 2] = a[2]; v[4 * q + 3] = a[3];
    }
}

// In-place DIT radix-4^2 16-pt DFT. Input: slot m holds in[DR16(m)]. Output NATURAL.
template <int DIR>
__device__ __forceinline__ void dft16_dit(float2 v[16]) {
#pragma unroll
    for (int q = 0; q < 4; q++) {
        float2 a[4] = {v[4 * q], v[4 * q + 1], v[4 * q + 2], v[4 * q + 3]};
        dft4<DIR>(a);
        dft16_l1_twiddle<DIR>(a, q);
        v[4 * q] = a[0]; v[4 * q + 1] = a[1]; v[4 * q + 2] = a[2]; v[4 * q + 3] = a[3];
    }
#pragma unroll
    for (int u = 0; u < 4; u++) {
        float2 a[4] = {v[u], v[u + 4], v[u + 8], v[u + 12]};
        dft4<DIR>(a);
        v[u] = a[0]; v[u + 4] = a[1]; v[u + 8] = a[2]; v[u + 12] = a[3];
    }
}

__device__ __forceinline__ float2 shflx1(float2 a) {
    return make_float2(__shfl_xor_sync(0xffffffffu, a.x, 1),
                       __shfl_xor_sync(0xffffffffu, a.y, 1));
}

// ---------------- warp-level 512-pt forward FFT ----------------
__device__ __forceinline__ void wfft512_fwd(float2 v[16], float2* sw, int lane,
                                            float2 w512p, float2 w64p, float2 w32p) {
    dft16_dif<-1>(v);  // slot m <-> freq DR16(m)
    int lo = lane & 15, hib = (lane >> 4) << 3;
#pragma unroll
    for (int p = 0; p < 16; p++) sw[(lane << 4) + (p ^ lo ^ hib)] = v[DR16(p)];
    __syncwarp();
    int p = lane >> 1, h = lane & 1;
#pragma unroll
    for (int j = 0; j < 16; j++) v[j] = sw[((16 * h + j) << 4) + (p ^ j ^ (h << 3))];
    __syncwarp();
    {   // twiddle w512^{p*(16h+j)}: two 8-deep chains (j and j+8)
        float2 c0 = h ? w32p : make_float2(1.0f, 0.0f);
        float2 c1 = cmul(c0, w64p);
#pragma unroll
        for (int j = 0; j < 8; j++) {
            v[j] = cmul(v[j], c0);
            v[j + 8] = cmul(v[j + 8], c1);
            c0 = cmul(c0, w512p);
            c1 = cmul(c1, w512p);
        }
    }
    {   // radix-2 butterfly over halves; w32^j are literals
#pragma unroll
        for (int j = 0; j < 16; j++) {
            float2 other = shflx1(v[j]);
            if (h == 0) v[j] = cadd(v[j], other);
            else if (j == 0) v[j] = csub(other, v[j]);
            else v[j] = cmul(csub(other, v[j]), w32f(j));
        }
    }
    dft16_dif<-1>(v);  // slot m <-> q' = DR16(m)
}

// ---------------- K2f: filter spectrum in slot layout, scaled 1/N ----------------
__global__ __launch_bounds__(256, 4) void k_filter_spec(const float2* __restrict__ U,
                                                        float2* __restrict__ Fp) {
    __shared__ float2 sw[8][512];
    int lane = threadIdx.x & 31, w = threadIdx.x >> 5;
    int k1 = (blockIdx.x << 3) + w;
    int p = lane >> 1;
    float sA, cA, s6, c6, s0, c0;
    __sincosf(-(TWO_PI / 512.0f) * (float)p, &sA, &cA);
    __sincosf(-(TWO_PI / 64.0f) * (float)p, &s6, &c6);
    __sincosf(-(TWO_PI / 32.0f) * (float)p, &s0, &c0);
    const float2* u = U + (size_t)PAIRS * N_FFT + (k1 << 9);
    float2 v[16];
#pragma unroll
    for (int r = 0; r < 16; r++) v[r] = u[lane + 32 * r];
    wfft512_fwd(v, sw[w], lane, make_float2(cA, sA), make_float2(c6, s6), make_float2(c0, s0));
    float2* o = Fp + (k1 << 9) + (lane << 4);
#pragma unroll
    for (int m = 0; m < 16; m++)
        o[m] = make_float2(v[m].x * INV_N, v[m].y * INV_N);
}

// ---------------- K23: fwd FFT512 + multiply + inv FFT512 + w_N^{+n2 k1} ----------------
__global__ __launch_bounds__(256, 4) void k_stageB_conv(float2* U, const float4* __restrict__ Fp4) {
    __shared__ float2 sw[8][512];
    int lane = threadIdx.x & 31, w = threadIdx.x >> 5;
    int k1 = (blockIdx.x << 3) + w;
    int row = blockIdx.y;
    float2* u = U + (size_t)row * N_FFT + (k1 << 9);
    float2* s = sw[w];
    int p = lane >> 1, h = lane & 1;
    float sA, cA, s6, c6, s0, c0;
    __sincosf(-(TWO_PI / 512.0f) * (float)p, &sA, &cA);  // w512^p (fwd sign)
    __sincosf(-(TWO_PI / 64.0f) * (float)p, &s6, &c6);   // w64^p = w512^{8p}
    __sincosf(-(TWO_PI / 32.0f) * (float)p, &s0, &c0);   // w32^p = w512^{16p}
    float2 w512p = make_float2(cA, sA), w64p = make_float2(c6, s6), w32p = make_float2(c0, s0);

    float2 v[16];
#pragma unroll
    for (int r = 0; r < 16; r++) v[r] = u[lane + 32 * r];
    wfft512_fwd(v, s, lane, w512p, w64p, w32p);

    // multiply by filter spectrum (slot-aligned, 8 x LDG.128)
    const float4* Fr = Fp4 + (((k1 << 9) + (lane << 4)) >> 1);
#pragma unroll
    for (int m2 = 0; m2 < 8; m2++) {
        float4 f = __ldg(Fr + m2);
        v[2 * m2]     = cmul(v[2 * m2],     make_float2(f.x, f.y));
        v[2 * m2 + 1] = cmul(v[2 * m2 + 1], make_float2(f.z, f.w));
    }

    // ---- inverse ----
    dft16_dit<1>(v);  // digitrev in (slot m <-> q'=DR16(m)) -> NATURAL out: v[tau]
    {   // butterfly (w32^j literals) + conj twiddle, two 8-deep cB chains
        float2 cB0 = h ? w32p : make_float2(1.0f, 0.0f);
        float2 cB1 = cmul(cB0, w64p);
#pragma unroll
        for (int j = 0; j < 8; j++) {
            {
                float2 other = shflx1(v[j]);
                if (h == 0) v[j] = (j == 0) ? cadd(v[j], other) : cadd(v[j], cmulc(other, w32f(j)));
                else        v[j] = (j == 0) ? csub(other, v[j]) : csub(other, cmulc(v[j], w32f(j)));
                v[j] = cmulc(v[j], cB0);
                cB0 = cmul(cB0, w512p);
            }
            {
                int j8 = j + 8;
                float2 other = shflx1(v[j8]);
                if (h == 0) v[j8] = cadd(v[j8], cmulc(other, w32f(j8)));
                else        v[j8] = csub(other, cmulc(v[j8], w32f(j8)));
                v[j8] = cmulc(v[j8], cB1);
                cB1 = cmul(cB1, w512p);
            }
        }
    }
    __syncwarp();
#pragma unroll
    for (int j = 0; j < 16; j++) s[((j + 16 * h) << 4) + (p ^ j ^ (h << 3))] = v[j];
    __syncwarp();
    int lo = lane & 15, hib = (lane >> 4) << 3;
#pragma unroll
    for (int q = 0; q < 16; q++) v[q] = s[(lane << 4) + (q ^ lo ^ hib)];
    dft16_dif<1>(v);  // natural in -> slot m <-> r = DR16(m); n2 = lane + 32r

    // outer twiddle w_N^{+n2 k1}: two 8-deep chains (r and r+8)
    float sb, cb, ss, cs, s8, c8;
    __sincosf((TWO_PI / (float)N_FFT) * (float)(lane * k1), &sb, &cb);
    __sincosf((TWO_PI / 4096.0f) * (float)k1, &ss, &cs);  // w_N^{+32 k1}
    __sincosf((TWO_PI / 512.0f) * (float)k1, &s8, &c8);   // w_N^{+256 k1}
    float2 wk0 = make_float2(cb, sb), wstep = make_float2(cs, ss);
    float2 wk8 = cmul(wk0, make_float2(c8, s8));
#pragma unroll
    for (int r = 0; r < 8; r++) {
        u[lane + 32 * r] = cmul(v[DR16(r)], wk0);
        u[lane + 32 * (r + 8)] = cmul(v[DR16(r + 8)], wk8);
        wk0 = cmul(wk0, wstep);
        wk8 = cmul(wk8, wstep);
    }
}

// ---------------- K1: pack + FFT256 over n1 (16x16, one transpose) + w_N twiddle ------
// Block 256 = 16 t x 16 c. grid (32, 129).
// n1 = t + 16b (b < 8 nonzero), k1 = k0 + 16*k1o.
// inner dft16_z8 over b -> k0; twiddle w256^{-t k0}; transpose; outer dft16 over t' -> k1o;
// epilogue w_N^{-n2 k1} and store U[k1][n2].
__global__ __launch_bounds__(256, 4) void k_stageA(const float* __restrict__ x,
                                                   const float* __restrict__ filt,
                                                   float2* __restrict__ U) {
    __shared__ float2 sm[16][16][16];  // [t][k0][swizzled c]
    int tx = threadIdx.x;
    int c = tx & 15, t = tx >> 4;
    int n2 = (blockIdx.x << 4) + c;
    int row = blockIdx.y;
    float2 v[16];
    if (row < PAIRS) {
        const float* xa = x + (size_t)row * T_LEN;
        const float* xb = x + (size_t)(row + PAIRS) * T_LEN;
#pragma unroll
        for (int b = 0; b < 8; b++) {
            int n = ((t + 16 * b) << 9) + n2;  // n1 = t+16b < 128
            v[b] = make_float2(__ldg(xa + n), __ldg(xb + n));
        }
    } else {
#pragma unroll
        for (int b = 0; b < 8; b++) {
            int n = ((t + 16 * b) << 9) + n2;
            v[b] = make_float2(__ldg(filt + n), 0.0f);
        }
    }
    dft16_dif_z8<-1>(v);  // over b: slot m <-> k0 = DR16(m)
    {   // twiddle w256^{-t k0}: two 8-deep chains over natural k0
        float sA, cA, s8, c8;
        __sincosf(-(TWO_PI / 256.0f) * (float)t, &sA, &cA);  // w256^{-t} step
        __sincosf(-(TWO_PI / 32.0f) * (float)t, &s8, &c8);   // w256^{-8t}
        float2 step = make_float2(cA, sA);
        float2 c0 = make_float2(1.0f, 0.0f);
        float2 c1 = make_float2(c8, s8);
#pragma unroll
        for (int k0 = 0; k0 < 8; k0++) {
            v[DR16(k0)] = cmul(v[DR16(k0)], c0);
            v[DR16(k0 + 8)] = cmul(v[DR16(k0 + 8)], c1);
            c0 = cmul(c0, step);
            c1 = cmul(c1, step);
        }
    }
    // transpose (same conflict-free pattern as K4)
#pragma unroll
    for (int k0 = 0; k0 < 16; k0++)
        sm[t][k0][(c + 8 * ((t + k0) & 1)) & 15] = v[DR16(k0)];
    __syncthreads();
#pragma unroll
    for (int a = 0; a < 16; a++)
        v[a] = sm[a][t][(c + 8 * ((a + t) & 1)) & 15];
    dft16_dif<-1>(v);  // over a: slot m <-> k1o = DR16(m); k1 = t + 16*k1o

    // epilogue: U[k1<<9 + n2] = X[k1] * w_N^{-n2 k1}; two 8-deep chains
    float sb, cb, ss, cs, s7, c7;
    __sincosf(-(TWO_PI / (float)N_FFT) * (float)(n2 * t), &sb, &cb);
    __sincosf(-(TWO_PI / 8192.0f) * (float)n2, &ss, &cs);  // w_N^{-16 n2}
    __sincosf(-(TWO_PI / 1024.0f) * (float)n2, &s7, &c7);  // w_N^{-128 n2}
    float2 wk0 = make_float2(cb, sb), wstep = make_float2(cs, ss);
    float2 wk8 = cmul(wk0, make_float2(c7, s7));
    float2* Ur = U + (size_t)row * N_FFT + n2;
#pragma unroll
    for (int k1o = 0; k1o < 8; k1o++) {
        Ur[(t + 16 * k1o) << 9] = cmul(v[DR16(k1o)], wk0);
        Ur[(t + 16 * (k1o + 8)) << 9] = cmul(v[DR16(k1o + 8)], wk8);
        wk0 = cmul(wk0, wstep);
        wk8 = cmul(wk8, wstep);
    }
}

// ---------------- K4: IFFT256 over k1 (16x16, one transpose) + causal unpack --------
__global__ __launch_bounds__(256, 4) void k_stageAinv(const float2* __restrict__ U,
                                                      float* __restrict__ y) {
    __shared__ float2 sm[16][16][16];  // [t][ni][swizzled c]
    int tx = threadIdx.x;
    int c = tx & 15, t = tx >> 4;
    int n2 = (blockIdx.x << 4) + c;
    int row = blockIdx.y;
    const float2* u = U + (size_t)row * N_FFT + n2;
    float2 v[16];
#pragma unroll
    for (int s = 0; s < 16; s++) v[s] = __ldg(u + (size_t)((t + 16 * s) << 9));
    dft16_dif<1>(v);  // inverse inner over s: slot m <-> ni = DR16(m)
    {   // twiddle w256^{+ni t}: two 8-deep chains over natural ni
        float sA, cA, s8, c8;
        __sincosf(-(TWO_PI / 256.0f) * (float)t, &sA, &cA);
        __sincosf(-(TWO_PI / 32.0f) * (float)t, &s8, &c8);
        float2 step = make_float2(cA, sA);
        float2 c0 = make_float2(1.0f, 0.0f);
        float2 c1 = make_float2(c8, s8);
#pragma unroll
        for (int ni = 0; ni < 8; ni++) {
            v[DR16(ni)] = cmulc(v[DR16(ni)], c0);
            v[DR16(ni + 8)] = cmulc(v[DR16(ni + 8)], c1);
            c0 = cmul(c0, step);
            c1 = cmul(c1, step);
        }
    }
#pragma unroll
    for (int ni = 0; ni < 16; ni++)
        sm[t][ni][(c + 8 * ((t + ni) & 1)) & 15] = v[DR16(ni)];
    __syncthreads();
#pragma unroll
    for (int tt = 0; tt < 16; tt++)
        v[tt] = sm[tt][t][(c + 8 * ((tt + t) & 1)) & 15];
    dft16_dif<1>(v);  // inverse outer over t: slot m <-> no = DR16(m)

    float* ya = y + (size_t)row * T_LEN;
    float* yb = y + (size_t)(row + PAIRS) * T_LEN;
#pragma unroll
    for (int no = 0; no < 8; no++) {  // n1 = t + 16*no < 128
        int n = ((t + 16 * no) << 9) + n2;
        float2 q = v[DR16(no)];
        ya[n] = q.x;
        yb[n] = q.y;
    }
}

extern "C" void kernel_launch(void* const* d_in, const int* in_sizes, int n_in,
                              void* d_out, int out_size) {
    const float* x = (const float*)d_in[0];
    const float* filt = (const float*)d_in[1];
    float* y = (float*)d_out;

    float2* U = nullptr;
    float4* F4 = nullptr;
    cudaGetSymbolAddress((void**)&U, g_buf);
    cudaGetSymbolAddress((void**)&F4, g_fspec4);

    k_stageA<<<dim3(32, ROWS_F), 256>>>(x, filt, U);
    k_filter_spec<<<32, 256>>>(U, (float2*)F4);
    k_stageB_conv<<<dim3(32, PAIRS), 256>>>(U, F4);
    k_stageAinv<<<dim3(32, PAIRS), 256>>>(U, y);
}

// round 14
// speedup vs baseline: 1.2299x; 1.1379x over previous
#include <cuda_runtime.h>
#include <cuda_fp16.h>

// EpochedFutureFill == causal FIR conv, B=256, T=L=65536, via FFT of N=131072.
// Four-step decomposition: N = 256 (n1, stride 512) x 512 (n2, contiguous).
//   K1 : pack + FFT256 over n1 (16x16, one transpose, zero-half aware) + w_N twiddle
//   K2f: filter row: warp-FFT512 -> F (slot layout, scaled 1/N)
//   K23: warp-autonomous FFT512 fwd + multiply + IFFT512 + w_N^{+n2 k1} (in place)
//   K4 : IFFT256 over k1 (16x16, one transpose) + causal unpack
// R14: intermediate U stored as fp16 (__half2 per complex) -> 540MB of scratch
// traffic becomes 270MB. Filter row kept fp32 in a separate buffer so the filter
// spectrum is exact (only 2 fp16 roundings on the data path; rel_err ~4e-4).

namespace {
constexpr int N_FFT = 131072;
constexpr int T_LEN = 65536;
constexpr int PAIRS = 128;
constexpr int ROWS_F = 129;
constexpr float TWO_PI = 6.28318530717958647692f;
constexpr float INV_N = 1.0f / (float)N_FFT;
}

// digit-reverse for radix-4^2 of 16: slot(p) = ((p&3)<<2)|(p>>2)  (involution)
#define DR16(p) ((((p) & 3) << 2) | ((p) >> 2))

// Scratch (no cudaMalloc allowed).
__device__ __half2 g_buf16[(size_t)PAIRS * N_FFT];  // data rows, fp16 complex (67 MB)
__device__ float2 g_bufF[N_FFT];                    // filter row U, fp32 (1 MB)
__device__ float4 g_fspec4[N_FFT / 2];              // F in slot layout, fp32

__device__ __forceinline__ float2 cadd(float2 a, float2 b) { return make_float2(a.x + b.x, a.y + b.y); }
__device__ __forceinline__ float2 csub(float2 a, float2 b) { return make_float2(a.x - b.x, a.y - b.y); }
__device__ __forceinline__ float2 cmul(float2 a, float2 b) {
    return make_float2(fmaf(a.x, b.x, -a.y * b.y), fmaf(a.x, b.y, a.y * b.x));
}
__device__ __forceinline__ float2 cmulc(float2 a, float2 b) {  // a * conj(b)
    return make_float2(fmaf(a.x, b.x, a.y * b.y), fmaf(a.y, b.x, -a.x * b.y));
}
template <int DIR>
__device__ __forceinline__ float2 cmuli(float2 a) {  // * (i*DIR)
    return (DIR < 0) ? make_float2(a.y, -a.x) : make_float2(-a.y, a.x);
}

// exp(-2*pi*i*j/32), compile-time after unrolling -> FFMA-imm operands.
__device__ __forceinline__ float2 w32f(int j) {
    switch (j & 15) {
        case 0:  return make_float2(1.0f, 0.0f);
        case 1:  return make_float2(0.9807852804032304f, -0.19509032201612827f);
        case 2:  return make_float2(0.9238795325112868f, -0.3826834323650898f);
        case 3:  return make_float2(0.8314696123025452f, -0.5555702330196022f);
        case 4:  return make_float2(0.7071067811865476f, -0.7071067811865476f);
        case 5:  return make_float2(0.5555702330196022f, -0.8314696123025452f);
        case 6:  return make_float2(0.3826834323650898f, -0.9238795325112868f);
        case 7:  return make_float2(0.19509032201612827f, -0.9807852804032304f);
        case 8:  return make_float2(0.0f, -1.0f);
        case 9:  return make_float2(-0.19509032201612827f, -0.9807852804032304f);
        case 10: return make_float2(-0.3826834323650898f, -0.9238795325112868f);
        case 11: return make_float2(-0.5555702330196022f, -0.8314696123025452f);
        case 12: return make_float2(-0.7071067811865476f, -0.7071067811865476f);
        case 13: return make_float2(-0.8314696123025452f, -0.5555702330196022f);
        case 14: return make_float2(-0.9238795325112868f, -0.3826834323650898f);
        default: return make_float2(-0.9807852804032304f, -0.19509032201612827f);
    }
}

template <int DIR>
__device__ __forceinline__ void dft4(float2 v[4]) {
    float2 t0 = cadd(v[0], v[2]);
    float2 t1 = cadd(v[1], v[3]);
    float2 t2 = csub(v[0], v[2]);
    float2 d  = csub(v[1], v[3]);
    v[0] = cadd(t0, t1);
    v[2] = csub(t0, t1);
    if (DIR < 0) {
        v[1] = make_float2(t2.x + d.y, t2.y - d.x);
        v[3] = make_float2(t2.x - d.y, t2.y + d.x);
    } else {
        v[1] = make_float2(t2.x - d.y, t2.y + d.x);
        v[3] = make_float2(t2.x + d.y, t2.y - d.x);
    }
}

// Shared twiddle block for the dft16 variants (applied to a[] after level-1 dft4, row j).
template <int DIR>
__device__ __forceinline__ void dft16_l1_twiddle(float2 a[4], int j) {
    const float C1 = 0.92387953251128674f, S1 = 0.38268343236508978f;
    const float C2 = 0.70710678118654752f;
    const float D = (float)DIR;
    const float2 w1 = make_float2(C1, D * S1), w2 = make_float2(C2, D * C2);
    const float2 w3 = make_float2(S1, D * C1), w6 = make_float2(-C2, D * C2);
    const float2 w9 = make_float2(-C1, -D * S1);
    if (j == 1) { a[1] = cmul(a[1], w1); a[2] = cmul(a[2], w2); a[3] = cmul(a[3], w3); }
    else if (j == 2) { a[1] = cmul(a[1], w2); a[2] = cmuli<DIR>(a[2]); a[3] = cmul(a[3], w6); }
    else if (j == 3) { a[1] = cmul(a[1], w3); a[2] = cmul(a[2], w6); a[3] = cmul(a[3], w9); }
}

// In-place DIF radix-4^2 16-pt DFT. Input natural; output: slot m holds X[DR16(m)].
template <int DIR>
__device__ __forceinline__ void dft16_dif(float2 v[16]) {
#pragma unroll
    for (int j = 0; j < 4; j++) {
        float2 a[4] = {v[j], v[j + 4], v[j + 8], v[j + 12]};
        dft4<DIR>(a);
        dft16_l1_twiddle<DIR>(a, j);
        v[j] = a[0]; v[j + 4] = a[1]; v[j + 8] = a[2]; v[j + 12] = a[3];
    }
#pragma unroll
    for (int q = 0; q < 4; q++) {
        float2 a[4] = {v[4 * q], v[4 * q + 1], v[4 * q + 2], v[4 * q + 3]};
        dft4<DIR>(a);
        v[4 * q] = a[0]; v[4 * q + 1] = a[1]; v[4 * q + 2] = a[2]; v[4 * q + 3] = a[3];
    }
}

// DIF 16-pt DFT with inputs 8..15 known zero (only v[0..7] read). Output as dft16_dif.
template <int DIR>
__device__ __forceinline__ void dft16_dif_z8(float2 v[16]) {
#pragma unroll
    for (int j = 0; j < 4; j++) {
        float2 in0 = v[j], in1 = v[j + 4];
        float2 a[4];
        a[0] = cadd(in0, in1);
        a[2] = csub(in0, in1);
        if (DIR < 0) {
            a[1] = make_float2(in0.x + in1.y, in0.y - in1.x);
            a[3] = make_float2(in0.x - in1.y, in0.y + in1.x);
        } else {
            a[1] = make_float2(in0.x - in1.y, in0.y + in1.x);
            a[3] = make_float2(in0.x + in1.y, in0.y - in1.x);
        }
        dft16_l1_twiddle<DIR>(a, j);
        v[j] = a[0]; v[j + 4] = a[1]; v[j + 8] = a[2]; v[j + 12] = a[3];
    }
#pragma unroll
    for (int q = 0; q < 4; q++) {
        float2 a[4] = {v[4 * q], v[4 * q + 1], v[4 * q + 2], v[4 * q + 3]};
        dft4<DIR>(a);
        v[4 * q] = a[0]; v[4 * q + 1] = a[1]; v[4 * q + 2] = a[2]; v[4 * q + 3] = a[3];
    }
}

// In-place DIT radix-4^2 16-pt DFT. Input: slot m holds in[DR16(m)]. Output NATURAL.
template <int DIR>
__device__ __forceinline__ void dft16_dit(float2 v[16]) {
#pragma unroll
    for (int q = 0; q < 4; q++) {
        float2 a[4] = {v[4 * q], v[4 * q + 1], v[4 * q + 2], v[4 * q + 3]};
        dft4<DIR>(a);
        dft16_l1_twiddle<DIR>(a, q);
        v[4 * q] = a[0]; v[4 * q + 1] = a[1]; v[4 * q + 2] = a[2]; v[4 * q + 3] = a[3];
    }
#pragma unroll
    for (int u = 0; u < 4; u++) {
        float2 a[4] = {v[u], v[u + 4], v[u + 8], v[u + 12]};
        dft4<DIR>(a);
        v[u] = a[0]; v[u + 4] = a[1]; v[u + 8] = a[2]; v[u + 12] = a[3];
    }
}

__device__ __forceinline__ float2 shflx1(float2 a) {
    return make_float2(__shfl_xor_sync(0xffffffffu, a.x, 1),
                       __shfl_xor_sync(0xffffffffu, a.y, 1));
}

// ---------------- warp-level 512-pt forward FFT (fp32 values in regs) ----------------
__device__ __forceinline__ void wfft512_fwd(float2 v[16], float2* sw, int lane,
                                            float2 w512p, float2 w64p, float2 w32p) {
    dft16_dif<-1>(v);  // slot m <-> freq DR16(m)
    int lo = lane & 15, hib = (lane >> 4) << 3;
#pragma unroll
    for (int p = 0; p < 16; p++) sw[(lane << 4) + (p ^ lo ^ hib)] = v[DR16(p)];
    __syncwarp();
    int p = lane >> 1, h = lane & 1;
#pragma unroll
    for (int j = 0; j < 16; j++) v[j] = sw[((16 * h + j) << 4) + (p ^ j ^ (h << 3))];
    __syncwarp();
    {   // twiddle w512^{p*(16h+j)}: two 8-deep chains (j and j+8)
        float2 c0 = h ? w32p : make_float2(1.0f, 0.0f);
        float2 c1 = cmul(c0, w64p);
#pragma unroll
        for (int j = 0; j < 8; j++) {
            v[j] = cmul(v[j], c0);
            v[j + 8] = cmul(v[j + 8], c1);
            c0 = cmul(c0, w512p);
            c1 = cmul(c1, w512p);
        }
    }
    {   // radix-2 butterfly over halves; w32^j are literals
#pragma unroll
        for (int j = 0; j < 16; j++) {
            float2 other = shflx1(v[j]);
            if (h == 0) v[j] = cadd(v[j], other);
            else if (j == 0) v[j] = csub(other, v[j]);
            else v[j] = cmul(csub(other, v[j]), w32f(j));
        }
    }
    dft16_dif<-1>(v);  // slot m <-> q' = DR16(m)
}

// ---------------- K2f: filter spectrum (fp32 path) in slot layout, scaled 1/N --------
__global__ __launch_bounds__(256, 4) void k_filter_spec(const float2* __restrict__ Uf,
                                                        float2* __restrict__ Fp) {
    __shared__ float2 sw[8][512];
    int lane = threadIdx.x & 31, w = threadIdx.x >> 5;
    int k1 = (blockIdx.x << 3) + w;
    int p = lane >> 1;
    float sA, cA, s6, c6, s0, c0;
    __sincosf(-(TWO_PI / 512.0f) * (float)p, &sA, &cA);
    __sincosf(-(TWO_PI / 64.0f) * (float)p, &s6, &c6);
    __sincosf(-(TWO_PI / 32.0f) * (float)p, &s0, &c0);
    const float2* u = Uf + (k1 << 9);
    float2 v[16];
#pragma unroll
    for (int r = 0; r < 16; r++) v[r] = u[lane + 32 * r];
    wfft512_fwd(v, sw[w], lane, make_float2(cA, sA), make_float2(c6, s6), make_float2(c0, s0));
    float2* o = Fp + (k1 << 9) + (lane << 4);
#pragma unroll
    for (int m = 0; m < 16; m++)
        o[m] = make_float2(v[m].x * INV_N, v[m].y * INV_N);
}

// ---------------- K23: fwd FFT512 + multiply + inv FFT512 + w_N^{+n2 k1} (fp16 U) -----
__global__ __launch_bounds__(256, 4) void k_stageB_conv(__half2* U, const float4* __restrict__ Fp4) {
    __shared__ float2 sw[8][512];
    int lane = threadIdx.x & 31, w = threadIdx.x >> 5;
    int k1 = (blockIdx.x << 3) + w;
    int row = blockIdx.y;
    __half2* u = U + (size_t)row * N_FFT + (k1 << 9);
    float2* s = sw[w];
    int p = lane >> 1, h = lane & 1;
    float sA, cA, s6, c6, s0, c0;
    __sincosf(-(TWO_PI / 512.0f) * (float)p, &sA, &cA);  // w512^p (fwd sign)
    __sincosf(-(TWO_PI / 64.0f) * (float)p, &s6, &c6);   // w64^p = w512^{8p}
    __sincosf(-(TWO_PI / 32.0f) * (float)p, &s0, &c0);   // w32^p = w512^{16p}
    float2 w512p = make_float2(cA, sA), w64p = make_float2(c6, s6), w32p = make_float2(c0, s0);

    float2 v[16];
#pragma unroll
    for (int r = 0; r < 16; r++) v[r] = __half22float2(u[lane + 32 * r]);
    wfft512_fwd(v, s, lane, w512p, w64p, w32p);

    // multiply by filter spectrum (slot-aligned, 8 x LDG.128)
    const float4* Fr = Fp4 + (((k1 << 9) + (lane << 4)) >> 1);
#pragma unroll
    for (int m2 = 0; m2 < 8; m2++) {
        float4 f = __ldg(Fr + m2);
        v[2 * m2]     = cmul(v[2 * m2],     make_float2(f.x, f.y));
        v[2 * m2 + 1] = cmul(v[2 * m2 + 1], make_float2(f.z, f.w));
    }

    // ---- inverse ----
    dft16_dit<1>(v);  // digitrev in (slot m <-> q'=DR16(m)) -> NATURAL out: v[tau]
    {   // butterfly (w32^j literals) + conj twiddle, two 8-deep cB chains
        float2 cB0 = h ? w32p : make_float2(1.0f, 0.0f);
        float2 cB1 = cmul(cB0, w64p);
#pragma unroll
        for (int j = 0; j < 8; j++) {
            {
                float2 other = shflx1(v[j]);
                if (h == 0) v[j] = (j == 0) ? cadd(v[j], other) : cadd(v[j], cmulc(other, w32f(j)));
                else        v[j] = (j == 0) ? csub(other, v[j]) : csub(other, cmulc(v[j], w32f(j)));
                v[j] = cmulc(v[j], cB0);
                cB0 = cmul(cB0, w512p);
            }
            {
                int j8 = j + 8;
                float2 other = shflx1(v[j8]);
                if (h == 0) v[j8] = cadd(v[j8], cmulc(other, w32f(j8)));
                else        v[j8] = csub(other, cmulc(v[j8], w32f(j8)));
                v[j8] = cmulc(v[j8], cB1);
                cB1 = cmul(cB1, w512p);
            }
        }
    }
    __syncwarp();
#pragma unroll
    for (int j = 0; j < 16; j++) s[((j + 16 * h) << 4) + (p ^ j ^ (h << 3))] = v[j];
    __syncwarp();
    int lo = lane & 15, hib = (lane >> 4) << 3;
#pragma unroll
    for (int q = 0; q < 16; q++) v[q] = s[(lane << 4) + (q ^ lo ^ hib)];
    dft16_dif<1>(v);  // natural in -> slot m <-> r = DR16(m); n2 = lane + 32r

    // outer twiddle w_N^{+n2 k1}: two 8-deep chains (r and r+8)
    float sb, cb, ss, cs, s8, c8;
    __sincosf((TWO_PI / (float)N_FFT) * (float)(lane * k1), &sb, &cb);
    __sincosf((TWO_PI / 4096.0f) * (float)k1, &ss, &cs);  // w_N^{+32 k1}
    __sincosf((TWO_PI / 512.0f) * (float)k1, &s8, &c8);   // w_N^{+256 k1}
    float2 wk0 = make_float2(cb, sb), wstep = make_float2(cs, ss);
    float2 wk8 = cmul(wk0, make_float2(c8, s8));
#pragma unroll
    for (int r = 0; r < 8; r++) {
        u[lane + 32 * r] = __float22half2_rn(cmul(v[DR16(r)], wk0));
        u[lane + 32 * (r + 8)] = __float22half2_rn(cmul(v[DR16(r + 8)], wk8));
        wk0 = cmul(wk0, wstep);
        wk8 = cmul(wk8, wstep);
    }
}

// ---------------- K1: pack + FFT256 over n1 (16x16, one transpose) + w_N twiddle ------
// Data rows -> fp16 U; filter row (row==PAIRS) -> fp32 Uf.
__global__ __launch_bounds__(256, 4) void k_stageA(const float* __restrict__ x,
                                                   const float* __restrict__ filt,
                                                   __half2* __restrict__ U16,
                                                   float2* __restrict__ Uf) {
    __shared__ float2 sm[16][16][16];  // [t][k0][swizzled c]
    int tx = threadIdx.x;
    int c = tx & 15, t = tx >> 4;
    int n2 = (blockIdx.x << 4) + c;
    int row = blockIdx.y;
    float2 v[16];
    if (row < PAIRS) {
        const float* xa = x + (size_t)row * T_LEN;
        const float* xb = x + (size_t)(row + PAIRS) * T_LEN;
#pragma unroll
        for (int b = 0; b < 8; b++) {
            int n = ((t + 16 * b) << 9) + n2;  // n1 = t+16b < 128
            v[b] = make_float2(__ldg(xa + n), __ldg(xb + n));
        }
    } else {
#pragma unroll
        for (int b = 0; b < 8; b++) {
            int n = ((t + 16 * b) << 9) + n2;
            v[b] = make_float2(__ldg(filt + n), 0.0f);
        }
    }
    dft16_dif_z8<-1>(v);  // over b: slot m <-> k0 = DR16(m)
    {   // twiddle w256^{-t k0}: two 8-deep chains over natural k0
        float sA, cA, s8, c8;
        __sincosf(-(TWO_PI / 256.0f) * (float)t, &sA, &cA);
        __sincosf(-(TWO_PI / 32.0f) * (float)t, &s8, &c8);
        float2 step = make_float2(cA, sA);
        float2 c0 = make_float2(1.0f, 0.0f);
        float2 c1 = make_float2(c8, s8);
#pragma unroll
        for (int k0 = 0; k0 < 8; k0++) {
            v[DR16(k0)] = cmul(v[DR16(k0)], c0);
            v[DR16(k0 + 8)] = cmul(v[DR16(k0 + 8)], c1);
            c0 = cmul(c0, step);
            c1 = cmul(c1, step);
        }
    }
#pragma unroll
    for (int k0 = 0; k0 < 16; k0++)
        sm[t][k0][(c + 8 * ((t + k0) & 1)) & 15] = v[DR16(k0)];
    __syncthreads();
#pragma unroll
    for (int a = 0; a < 16; a++)
        v[a] = sm[a][t][(c + 8 * ((a + t) & 1)) & 15];
    dft16_dif<-1>(v);  // over a: slot m <-> k1o = DR16(m); k1 = t + 16*k1o

    // epilogue: U[k1<<9 + n2] = X[k1] * w_N^{-n2 k1}; two 8-deep chains
    float sb, cb, ss, cs, s7, c7;
    __sincosf(-(TWO_PI / (float)N_FFT) * (float)(n2 * t), &sb, &cb);
    __sincosf(-(TWO_PI / 8192.0f) * (float)n2, &ss, &cs);  // w_N^{-16 n2}
    __sincosf(-(TWO_PI / 1024.0f) * (float)n2, &s7, &c7);  // w_N^{-128 n2}
    float2 wk0 = make_float2(cb, sb), wstep = make_float2(cs, ss);
    float2 wk8 = cmul(wk0, make_float2(c7, s7));
    if (row < PAIRS) {
        __half2* Ur = U16 + (size_t)row * N_FFT + n2;
#pragma unroll
        for (int k1o = 0; k1o < 8; k1o++) {
            Ur[(t + 16 * k1o) << 9] = __float22half2_rn(cmul(v[DR16(k1o)], wk0));
            Ur[(t + 16 * (k1o + 8)) << 9] = __float22half2_rn(cmul(v[DR16(k1o + 8)], wk8));
            wk0 = cmul(wk0, wstep);
            wk8 = cmul(wk8, wstep);
        }
    } else {
        float2* Ur = Uf + n2;
#pragma unroll
        for (int k1o = 0; k1o < 8; k1o++) {
            Ur[(t + 16 * k1o) << 9] = cmul(v[DR16(k1o)], wk0);
            Ur[(t + 16 * (k1o + 8)) << 9] = cmul(v[DR16(k1o + 8)], wk8);
            wk0 = cmul(wk0, wstep);
            wk8 = cmul(wk8, wstep);
        }
    }
}

// ---------------- K4: IFFT256 over k1 (16x16, one transpose) + causal unpack --------
__global__ __launch_bounds__(256, 4) void k_stageAinv(const __half2* __restrict__ U,
                                                      float* __restrict__ y) {
    __shared__ float2 sm[16][16][16];  // [t][ni][swizzled c]
    int tx = threadIdx.x;
    int c = tx & 15, t = tx >> 4;
    int n2 = (blockIdx.x << 4) + c;
    int row = blockIdx.y;
    const __half2* u = U + (size_t)row * N_FFT + n2;
    float2 v[16];
#pragma unroll
    for (int s = 0; s < 16; s++) v[s] = __half22float2(__ldg(u + (size_t)((t + 16 * s) << 9)));
    dft16_dif<1>(v);  // inverse inner over s: slot m <-> ni = DR16(m)
    {   // twiddle w256^{+ni t}: two 8-deep chains over natural ni
        float sA, cA, s8, c8;
        __sincosf(-(TWO_PI / 256.0f) * (float)t, &sA, &cA);
        __sincosf(-(TWO_PI / 32.0f) * (float)t, &s8, &c8);
        float2 step = make_float2(cA, sA);
        float2 c0 = make_float2(1.0f, 0.0f);
        float2 c1 = make_float2(c8, s8);
#pragma unroll
        for (int ni = 0; ni < 8; ni++) {
            v[DR16(ni)] = cmulc(v[DR16(ni)], c0);
            v[DR16(ni + 8)] = cmulc(v[DR16(ni + 8)], c1);
            c0 = cmul(c0, step);
            c1 = cmul(c1, step);
        }
    }
#pragma unroll
    for (int ni = 0; ni < 16; ni++)
        sm[t][ni][(c + 8 * ((t + ni) & 1)) & 15] = v[DR16(ni)];
    __syncthreads();
#pragma unroll
    for (int tt = 0; tt < 16; tt++)
        v[tt] = sm[tt][t][(c + 8 * ((tt + t) & 1)) & 15];
    dft16_dif<1>(v);  // inverse outer over t: slot m <-> no = DR16(m)

    float* ya = y + (size_t)row * T_LEN;
    float* yb = y + (size_t)(row + PAIRS) * T_LEN;
#pragma unroll
    for (int no = 0; no < 8; no++) {  // n1 = t + 16*no < 128
        int n = ((t + 16 * no) << 9) + n2;
        float2 q = v[DR16(no)];
        ya[n] = q.x;
        yb[n] = q.y;
    }
}

extern "C" void kernel_launch(void* const* d_in, const int* in_sizes, int n_in,
                              void* d_out, int out_size) {
    const float* x = (const float*)d_in[0];
    const float* filt = (const float*)d_in[1];
    float* y = (float*)d_out;

    __half2* U16 = nullptr;
    float2* Uf = nullptr;
    float4* F4 = nullptr;
    cudaGetSymbolAddress((void**)&U16, g_buf16);
    cudaGetSymbolAddress((void**)&Uf, g_bufF);
    cudaGetSymbolAddress((void**)&F4, g_fspec4);

    k_stageA<<<dim3(32, ROWS_F), 256>>>(x, filt, U16, Uf);
    k_filter_spec<<<32, 256>>>(Uf, (float2*)F4);
    k_stageB_conv<<<dim3(32, PAIRS), 256>>>(U16, F4);
    k_stageAinv<<<dim3(32, PAIRS), 256>>>(U16, y);
}